// round 1
// baseline (speedup 1.0000x reference)
#include <cuda_runtime.h>

#define N_ROWS 131072
#define D      64
#define KFULL  1024
#define KM1    1023
#define TJ     16

// Scratch (no dynamic allocation allowed)
__device__ float g_dith[KFULL * D];   // row 1023 = zeros (padding)
__device__ float g_cj[KFULL];         // ||d_j||^2, entry 1023 = 1e30 (never wins)
__device__ int   g_counts[KFULL];

// ---------- packed f32x2 helpers (Blackwell FFMA2 path) ----------
__device__ __forceinline__ unsigned long long pk2(float a, float b) {
    unsigned long long r;
    asm("mov.b64 %0, {%1,%2};" : "=l"(r) : "f"(a), "f"(b));
    return r;
}
__device__ __forceinline__ unsigned long long fma2(unsigned long long a,
                                                   unsigned long long b,
                                                   unsigned long long c) {
    unsigned long long d;
    asm("fma.rn.f32x2 %0, %1, %2, %3;" : "=l"(d) : "l"(a), "l"(b), "l"(c));
    return d;
}
__device__ __forceinline__ float2 upk(unsigned long long r) {
    float2 f;
    asm("mov.b64 {%0,%1}, %2;" : "=f"(f.x), "=f"(f.y) : "l"(r));
    return f;
}

// ---------- prep: dithered codebook (separate RN ops, no FMA contraction) ----------
__global__ void prep_kernel(const float* __restrict__ cb,
                            const float* __restrict__ dither) {
    int idx = blockIdx.x * blockDim.x + threadIdx.x;
    if (idx < KFULL * D) {
        int j = idx / D, k = idx % D;
        float v = 0.0f;
        if (j < KM1) {
            float lo = cb[j * D + k];
            float hi = cb[(j + 1) * D + k];
            float t  = __fsub_rn(hi, lo);
            float u  = __fmul_rn(dither[j], t);
            v        = __fadd_rn(lo, u);
        }
        g_dith[idx] = v;
    }
    if (idx < KFULL) g_counts[idx] = 0;
}

// ---------- ||d_j||^2, sequential fp32 sum (match jnp.sum order guess) ----------
__global__ void cj_kernel() {
    int j = blockIdx.x * blockDim.x + threadIdx.x;
    if (j >= KFULL) return;
    if (j >= KM1) { g_cj[j] = 1e30f; return; }
    float acc = 0.0f;
    #pragma unroll
    for (int k = 0; k < D; k++) {
        float d = g_dith[j * D + k];
        acc = __fadd_rn(acc, __fmul_rn(d, d));
    }
    g_cj[j] = acc;
}

// ---------- main: argmin over 1023 codes + full epilogue, one row per thread ----------
__global__ void __launch_bounds__(256)
main_kernel(const float* __restrict__ z,
            const float* __restrict__ cb,
            const float* __restrict__ dither,
            const float* __restrict__ n1,
            const float* __restrict__ n2,
            float* __restrict__ out) {
    __shared__ __align__(16) float sd[TJ * D];
    __shared__ float sc[TJ];

    const int row = blockIdx.x * 256 + threadIdx.x;

    // Load z row, compute ||z||^2 sequentially (RN, no contraction)
    float zr[D];
    {
        const float4* zp = (const float4*)(z + (size_t)row * D);
        #pragma unroll
        for (int q = 0; q < 16; q++) {
            float4 v = zp[q];
            zr[4 * q + 0] = v.x; zr[4 * q + 1] = v.y;
            zr[4 * q + 2] = v.z; zr[4 * q + 3] = v.w;
        }
    }
    float nz = 0.0f;
    #pragma unroll
    for (int k = 0; k < D; k++) nz = __fadd_rn(nz, __fmul_rn(zr[k], zr[k]));

    // Pack z into f32x2 pairs
    unsigned long long z2[32];
    #pragma unroll
    for (int q = 0; q < 32; q++) z2[q] = pk2(zr[2 * q], zr[2 * q + 1]);

    float best = 3.4e38f;
    int   bidx = 0;

    for (int jt = 0; jt < KFULL / TJ; jt++) {
        __syncthreads();
        // cooperative tile load: 16 codes x 64 floats = 256 float4
        ((float4*)sd)[threadIdx.x] =
            ((const float4*)(g_dith + (size_t)jt * TJ * D))[threadIdx.x];
        if (threadIdx.x < TJ) sc[threadIdx.x] = g_cj[jt * TJ + threadIdx.x];
        __syncthreads();

        #pragma unroll
        for (int c = 0; c < TJ; c++) {
            const ulonglong2* sp = (const ulonglong2*)(sd + c * D);
            unsigned long long a0 = 0ull, a1 = 0ull, a2 = 0ull, a3 = 0ull;
            #pragma unroll
            for (int q = 0; q < 16; q += 2) {
                ulonglong2 v0 = sp[q];
                ulonglong2 v1 = sp[q + 1];
                a0 = fma2(z2[2 * q + 0], v0.x, a0);
                a1 = fma2(z2[2 * q + 1], v0.y, a1);
                a2 = fma2(z2[2 * q + 2], v1.x, a2);
                a3 = fma2(z2[2 * q + 3], v1.y, a3);
            }
            float2 f0 = upk(a0), f1 = upk(a1), f2 = upk(a2), f3 = upk(a3);
            float dot = ((f0.x + f0.y) + (f1.x + f1.y)) +
                        ((f2.x + f2.y) + (f3.x + f3.y));
            // s = RN(RN(nz + c_j) - RN(2*dot))  -- matches reference structure
            float s = __fsub_rn(__fadd_rn(nz, sc[c]), __fmul_rn(2.0f, dot));
            int j = jt * TJ + c;
            if (s < best) { best = s; bidx = j; }
        }
    }

    // ---------- epilogue ----------
    const int i = bidx;
    const float2* cfp = (const float2*)(cb + (size_t)i * D);
    const float2* csp = (const float2*)(cb + (size_t)(i + 1) * D);
    const float2* ap  = (const float2*)(n1 + (size_t)row * D);
    const float2* bp  = (const float2*)(n2 + (size_t)row * D);
    const float lam = dither[i];

    // pass A: sums (sequential order over k)
    float sd1 = 0.0f, sr1 = 0.0f, sd2 = 0.0f, sr2 = 0.0f;
    #pragma unroll
    for (int q = 0; q < 32; q++) {
        float2 zz = upk(z2[q]);
        float2 cf = cfp[q], cs = csp[q], av = ap[q], bv = bp[q];
        {
            float d1 = __fsub_rn(cf.x, zz.x);
            float r1 = __fadd_rn(av.x, d1);
            sd1 = __fadd_rn(sd1, __fmul_rn(d1, d1));
            sr1 = __fadd_rn(sr1, __fmul_rn(r1, r1));
            float d2 = __fsub_rn(cs.x, zz.x);
            float r2 = __fadd_rn(bv.x, d2);
            sd2 = __fadd_rn(sd2, __fmul_rn(d2, d2));
            sr2 = __fadd_rn(sr2, __fmul_rn(r2, r2));
        }
        {
            float d1 = __fsub_rn(cf.y, zz.y);
            float r1 = __fadd_rn(av.y, d1);
            sd1 = __fadd_rn(sd1, __fmul_rn(d1, d1));
            sr1 = __fadd_rn(sr1, __fmul_rn(r1, r1));
            float d2 = __fsub_rn(cs.y, zz.y);
            float r2 = __fadd_rn(bv.y, d2);
            sd2 = __fadd_rn(sd2, __fmul_rn(d2, d2));
            sr2 = __fadd_rn(sr2, __fmul_rn(r2, r2));
        }
    }

    float nn1 = fmaxf(__fsqrt_rn(sr1), 1e-12f);
    float nn2 = fmaxf(__fsqrt_rn(sr2), 1e-12f);
    float em1 = __fsqrt_rn(sd1);
    float em2 = __fsqrt_rn(sd2);
    float s1  = __fsub_rn(1.0f, lam);

    // pass B: z_q, replicating reference op order:
    // z_q = (z + em1*((1-lam)*(rv1/n1))) + em2*(lam*(rv2/n2))
    float2* op = (float2*)(out + (size_t)row * D);
    #pragma unroll
    for (int q = 0; q < 32; q++) {
        float2 zz = upk(z2[q]);
        float2 cf = cfp[q], cs = csp[q], av = ap[q], bv = bp[q];
        float2 o;
        {
            float d1 = __fsub_rn(cf.x, zz.x);
            float r1 = __fadd_rn(av.x, d1);
            float d2 = __fsub_rn(cs.x, zz.x);
            float r2 = __fadd_rn(bv.x, d2);
            float v1 = __fmul_rn(em1, __fmul_rn(s1,  __fdiv_rn(r1, nn1)));
            float v2 = __fmul_rn(em2, __fmul_rn(lam, __fdiv_rn(r2, nn2)));
            o.x = __fadd_rn(__fadd_rn(zz.x, v1), v2);
        }
        {
            float d1 = __fsub_rn(cf.y, zz.y);
            float r1 = __fadd_rn(av.y, d1);
            float d2 = __fsub_rn(cs.y, zz.y);
            float r2 = __fadd_rn(bv.y, d2);
            float v1 = __fmul_rn(em1, __fmul_rn(s1,  __fdiv_rn(r1, nn1)));
            float v2 = __fmul_rn(em2, __fmul_rn(lam, __fdiv_rn(r2, nn2)));
            o.y = __fadd_rn(__fadd_rn(zz.y, v1), v2);
        }
        op[q] = o;
    }

    out[(size_t)N_ROWS * D + row] = (float)i;
    atomicAdd(&g_counts[i], 1);
}

// ---------- perplexity ----------
__global__ void perp_kernel(float* __restrict__ out) {
    __shared__ float sh[1024];
    int t = threadIdx.x;
    float p = (float)g_counts[t] * (1.0f / 131072.0f);  // /2^17 exact
    sh[t] = (p > 0.0f) ? __fmul_rn(p, logf(p)) : 0.0f;
    __syncthreads();
    for (int s = 512; s > 0; s >>= 1) {
        if (t < s) sh[t] = __fadd_rn(sh[t], sh[t + s]);
        __syncthreads();
    }
    if (t == 0) out[(size_t)N_ROWS * D + N_ROWS] = expf(-sh[0]);
}

extern "C" void kernel_launch(void* const* d_in, const int* in_sizes, int n_in,
                              void* d_out, int out_size) {
    const float* z      = (const float*)d_in[0];
    const float* cb     = (const float*)d_in[1];
    const float* dither = (const float*)d_in[2];
    const float* n1     = (const float*)d_in[3];
    const float* n2     = (const float*)d_in[4];
    float* out = (float*)d_out;

    prep_kernel<<<(KFULL * D + 255) / 256, 256>>>(cb, dither);
    cj_kernel<<<4, 256>>>();
    main_kernel<<<N_ROWS / 256, 256>>>(z, cb, dither, n1, n2, out);
    perp_kernel<<<1, 1024>>>(out);
}

// round 2
// speedup vs baseline: 1.2528x; 1.2528x over previous
#include <cuda_runtime.h>

#define N_ROWS 131072
#define D      64
#define KFULL  1024
#define KM1    1023
#define TJ     16
#define TPB    128
#define RPB    256   // rows per block (2 per thread)

// Scratch (no dynamic allocation allowed)
__device__ float g_dith[KFULL * D];   // row 1023 = zeros (padding)
__device__ float g_cj[KFULL];         // ||d_j||^2, entry 1023 = 1e30 (never wins)
__device__ int   g_counts[KFULL];

// ---------- packed f32x2 helpers ----------
__device__ __forceinline__ unsigned long long fma2(unsigned long long a,
                                                   unsigned long long b,
                                                   unsigned long long c) {
    unsigned long long d;
    asm("fma.rn.f32x2 %0, %1, %2, %3;" : "=l"(d) : "l"(a), "l"(b), "l"(c));
    return d;
}
__device__ __forceinline__ float2 upk(unsigned long long r) {
    float2 f;
    asm("mov.b64 {%0,%1}, %2;" : "=f"(f.x), "=f"(f.y) : "l"(r));
    return f;
}

// ---------- prep: dithered codebook (separate RN ops, no FMA contraction) ----------
__global__ void prep_kernel(const float* __restrict__ cb,
                            const float* __restrict__ dither) {
    int idx = blockIdx.x * blockDim.x + threadIdx.x;
    if (idx < KFULL * D) {
        int j = idx / D, k = idx % D;
        float v = 0.0f;
        if (j < KM1) {
            float lo = cb[j * D + k];
            float hi = cb[(j + 1) * D + k];
            float t  = __fsub_rn(hi, lo);
            float u  = __fmul_rn(dither[j], t);
            v        = __fadd_rn(lo, u);
        }
        g_dith[idx] = v;
    }
    if (idx < KFULL) g_counts[idx] = 0;
}

// ---------- ||d_j||^2, sequential fp32 sum ----------
__global__ void cj_kernel() {
    int j = blockIdx.x * blockDim.x + threadIdx.x;
    if (j >= KFULL) return;
    if (j >= KM1) { g_cj[j] = 1e30f; return; }
    float acc = 0.0f;
    #pragma unroll
    for (int k = 0; k < D; k++) {
        float d = g_dith[j * D + k];
        acc = __fadd_rn(acc, __fmul_rn(d, d));
    }
    g_cj[j] = acc;
}

// ---------- per-row epilogue (identical numerics to R1) ----------
__device__ __forceinline__ void epilogue(int row, const unsigned long long* z2,
                                         int i,
                                         const float* __restrict__ cb,
                                         const float* __restrict__ dither,
                                         const float* __restrict__ n1,
                                         const float* __restrict__ n2,
                                         float* __restrict__ out) {
    const float2* cfp = (const float2*)(cb + (size_t)i * D);
    const float2* csp = (const float2*)(cb + (size_t)(i + 1) * D);
    const float2* ap  = (const float2*)(n1 + (size_t)row * D);
    const float2* bp  = (const float2*)(n2 + (size_t)row * D);
    const float lam = dither[i];

    float sd1 = 0.0f, sr1 = 0.0f, sd2 = 0.0f, sr2 = 0.0f;
    #pragma unroll
    for (int q = 0; q < 32; q++) {
        float2 zz = upk(z2[q]);
        float2 cf = cfp[q], cs = csp[q], av = ap[q], bv = bp[q];
        {
            float d1 = __fsub_rn(cf.x, zz.x);
            float r1 = __fadd_rn(av.x, d1);
            sd1 = __fadd_rn(sd1, __fmul_rn(d1, d1));
            sr1 = __fadd_rn(sr1, __fmul_rn(r1, r1));
            float d2 = __fsub_rn(cs.x, zz.x);
            float r2 = __fadd_rn(bv.x, d2);
            sd2 = __fadd_rn(sd2, __fmul_rn(d2, d2));
            sr2 = __fadd_rn(sr2, __fmul_rn(r2, r2));
        }
        {
            float d1 = __fsub_rn(cf.y, zz.y);
            float r1 = __fadd_rn(av.y, d1);
            sd1 = __fadd_rn(sd1, __fmul_rn(d1, d1));
            sr1 = __fadd_rn(sr1, __fmul_rn(r1, r1));
            float d2 = __fsub_rn(cs.y, zz.y);
            float r2 = __fadd_rn(bv.y, d2);
            sd2 = __fadd_rn(sd2, __fmul_rn(d2, d2));
            sr2 = __fadd_rn(sr2, __fmul_rn(r2, r2));
        }
    }

    float nn1 = fmaxf(__fsqrt_rn(sr1), 1e-12f);
    float nn2 = fmaxf(__fsqrt_rn(sr2), 1e-12f);
    float em1 = __fsqrt_rn(sd1);
    float em2 = __fsqrt_rn(sd2);
    float s1  = __fsub_rn(1.0f, lam);

    float2* op = (float2*)(out + (size_t)row * D);
    #pragma unroll
    for (int q = 0; q < 32; q++) {
        float2 zz = upk(z2[q]);
        float2 cf = cfp[q], cs = csp[q], av = ap[q], bv = bp[q];
        float2 o;
        {
            float d1 = __fsub_rn(cf.x, zz.x);
            float r1 = __fadd_rn(av.x, d1);
            float d2 = __fsub_rn(cs.x, zz.x);
            float r2 = __fadd_rn(bv.x, d2);
            float v1 = __fmul_rn(em1, __fmul_rn(s1,  __fdiv_rn(r1, nn1)));
            float v2 = __fmul_rn(em2, __fmul_rn(lam, __fdiv_rn(r2, nn2)));
            o.x = __fadd_rn(__fadd_rn(zz.x, v1), v2);
        }
        {
            float d1 = __fsub_rn(cf.y, zz.y);
            float r1 = __fadd_rn(av.y, d1);
            float d2 = __fsub_rn(cs.y, zz.y);
            float r2 = __fadd_rn(bv.y, d2);
            float v1 = __fmul_rn(em1, __fmul_rn(s1,  __fdiv_rn(r1, nn1)));
            float v2 = __fmul_rn(em2, __fmul_rn(lam, __fdiv_rn(r2, nn2)));
            o.y = __fadd_rn(__fadd_rn(zz.y, v1), v2);
        }
        op[q] = o;
    }

    out[(size_t)N_ROWS * D + row] = (float)i;
    atomicAdd(&g_counts[i], 1);
}

// ---------- main: 2 rows per thread, argmin over 1023 codes + epilogue ----------
__global__ void __launch_bounds__(TPB, 2)
main_kernel(const float* __restrict__ z,
            const float* __restrict__ cb,
            const float* __restrict__ dither,
            const float* __restrict__ n1,
            const float* __restrict__ n2,
            float* __restrict__ out) {
    __shared__ __align__(16) float sd[TJ * D];
    __shared__ float sc[TJ];

    const int rowA = blockIdx.x * RPB + threadIdx.x;
    const int rowB = rowA + TPB;

    // z rows loaded directly as f32x2 pairs (memory layout == pair layout)
    unsigned long long za[32], zb[32];
    {
        const ulonglong2* pa = (const ulonglong2*)(z + (size_t)rowA * D);
        const ulonglong2* pb = (const ulonglong2*)(z + (size_t)rowB * D);
        #pragma unroll
        for (int q = 0; q < 16; q++) {
            ulonglong2 va = pa[q]; za[2 * q] = va.x; za[2 * q + 1] = va.y;
            ulonglong2 vb = pb[q]; zb[2 * q] = vb.x; zb[2 * q + 1] = vb.y;
        }
    }

    // ||z||^2 sequential RN (same order as R1)
    float nzA = 0.0f, nzB = 0.0f;
    #pragma unroll
    for (int q = 0; q < 32; q++) {
        float2 a = upk(za[q]);
        nzA = __fadd_rn(nzA, __fmul_rn(a.x, a.x));
        nzA = __fadd_rn(nzA, __fmul_rn(a.y, a.y));
    }
    #pragma unroll
    for (int q = 0; q < 32; q++) {
        float2 b = upk(zb[q]);
        nzB = __fadd_rn(nzB, __fmul_rn(b.x, b.x));
        nzB = __fadd_rn(nzB, __fmul_rn(b.y, b.y));
    }

    float bestA = 3.4e38f, bestB = 3.4e38f;
    int   idxA = 0, idxB = 0;

    for (int jt = 0; jt < KFULL / TJ; jt++) {
        __syncthreads();
        // cooperative tile load: 16 codes x 64 floats = 256 float4, 128 threads
        {
            const float4* gsrc = (const float4*)(g_dith + (size_t)jt * TJ * D);
            ((float4*)sd)[threadIdx.x]       = gsrc[threadIdx.x];
            ((float4*)sd)[threadIdx.x + TPB] = gsrc[threadIdx.x + TPB];
            if (threadIdx.x < TJ) sc[threadIdx.x] = g_cj[jt * TJ + threadIdx.x];
        }
        __syncthreads();

        #pragma unroll
        for (int c = 0; c < TJ; c++) {
            const ulonglong2* sp = (const ulonglong2*)(sd + c * D);
            unsigned long long a0 = 0ull, a1 = 0ull, a2 = 0ull, a3 = 0ull;
            unsigned long long b0 = 0ull, b1 = 0ull, b2 = 0ull, b3 = 0ull;
            #pragma unroll
            for (int q = 0; q < 16; q += 2) {
                ulonglong2 v0 = sp[q];
                ulonglong2 v1 = sp[q + 1];
                a0 = fma2(za[2 * q + 0], v0.x, a0);
                b0 = fma2(zb[2 * q + 0], v0.x, b0);
                a1 = fma2(za[2 * q + 1], v0.y, a1);
                b1 = fma2(zb[2 * q + 1], v0.y, b1);
                a2 = fma2(za[2 * q + 2], v1.x, a2);
                b2 = fma2(zb[2 * q + 2], v1.x, b2);
                a3 = fma2(za[2 * q + 3], v1.y, a3);
                b3 = fma2(zb[2 * q + 3], v1.y, b3);
            }
            const int j = jt * TJ + c;
            const float scc = sc[c];
            {
                float2 f0 = upk(a0), f1 = upk(a1), f2 = upk(a2), f3 = upk(a3);
                float dot = ((f0.x + f0.y) + (f1.x + f1.y)) +
                            ((f2.x + f2.y) + (f3.x + f3.y));
                float s = __fsub_rn(__fadd_rn(nzA, scc), __fmul_rn(2.0f, dot));
                if (s < bestA) { bestA = s; idxA = j; }
            }
            {
                float2 f0 = upk(b0), f1 = upk(b1), f2 = upk(b2), f3 = upk(b3);
                float dot = ((f0.x + f0.y) + (f1.x + f1.y)) +
                            ((f2.x + f2.y) + (f3.x + f3.y));
                float s = __fsub_rn(__fadd_rn(nzB, scc), __fmul_rn(2.0f, dot));
                if (s < bestB) { bestB = s; idxB = j; }
            }
        }
    }

    epilogue(rowA, za, idxA, cb, dither, n1, n2, out);
    epilogue(rowB, zb, idxB, cb, dither, n1, n2, out);
}

// ---------- perplexity ----------
__global__ void perp_kernel(float* __restrict__ out) {
    __shared__ float sh[1024];
    int t = threadIdx.x;
    float p = (float)g_counts[t] * (1.0f / 131072.0f);
    sh[t] = (p > 0.0f) ? __fmul_rn(p, logf(p)) : 0.0f;
    __syncthreads();
    for (int s = 512; s > 0; s >>= 1) {
        if (t < s) sh[t] = __fadd_rn(sh[t], sh[t + s]);
        __syncthreads();
    }
    if (t == 0) out[(size_t)N_ROWS * D + N_ROWS] = expf(-sh[0]);
}

extern "C" void kernel_launch(void* const* d_in, const int* in_sizes, int n_in,
                              void* d_out, int out_size) {
    const float* z      = (const float*)d_in[0];
    const float* cb     = (const float*)d_in[1];
    const float* dither = (const float*)d_in[2];
    const float* n1     = (const float*)d_in[3];
    const float* n2     = (const float*)d_in[4];
    float* out = (float*)d_out;

    prep_kernel<<<(KFULL * D + 255) / 256, 256>>>(cb, dither);
    cj_kernel<<<4, 256>>>();
    main_kernel<<<N_ROWS / RPB, TPB>>>(z, cb, dither, n1, n2, out);
    perp_kernel<<<1, 1024>>>(out);
}